// round 11
// baseline (speedup 1.0000x reference)
#include <cuda_runtime.h>
#include <cstdint>

// Twist2Mat (Rodrigues): twist [B,R,3] f32 -> rot [B,R,3,3] f32
// N = B*R = 8,388,608. Memory-bound: 384 MB streaming (96 read / 288 write).
//
// R1: strided per-thread stores -> 9x L1 wf amplification (166us).
// R2: block smem staging, coalesced I/O (66.3us, DRAM 68%).
// R3: warp-private tiles + __ldcs/__stcs (63.9us).
// R4/R5: prefetch / read-MLP batching — neutral.
// R6: TMA bulk stores (harness 63.9, profile 58.7, DRAM 73.8%).
// R7: TMA bulk loads — neutral-negative; LDG loads kept.
// R9: paired 2304B stores (harness 63.55, profile 58.6, DRAM 74.0%).
//     Occupancy 72->39% with zero perf delta => purely BW-bound.
// R10: ONE 4608B bulk store per warp (1 dispatch, 1 fence) and exit drain via
//      wait_group.READ 0 (smem-read completion only, not write visibility) so
//      warps retire without tail-blocking on DRAM write latency.

#ifndef TPB
#define TPB 256
#endif
#define WARPS (TPB / 32)
#define TILES 4            // 32-element tiles per warp => 128 elems/warp

__device__ __forceinline__ void rodrigues9(float x, float y, float z, float* __restrict__ r)
{
    float n2    = fmaf(x, x, fmaf(y, y, z * z));
    float theta = fmaxf(sqrtf(n2), 1e-5f);
    float inv   = __fdividef(1.0f, theta);
    float a0 = x * inv, a1 = y * inv, a2 = z * inv;

    float s, c;
    __sincosf(theta, &s, &c);
    float k = 1.0f - c;

    // R = c*I + s*[a]_x + k*(a a^T)
    float ka0 = k * a0, ka1 = k * a1;
    float sa0 = s * a0, sa1 = s * a1, sa2 = s * a2;

    r[0] = fmaf(ka0, a0, c);
    r[1] = fmaf(ka0, a1, -sa2);
    r[2] = fmaf(ka0, a2,  sa1);
    r[3] = fmaf(ka0, a1,  sa2);
    r[4] = fmaf(ka1, a1, c);
    r[5] = fmaf(ka1, a2, -sa0);
    r[6] = fmaf(ka0, a2, -sa1);
    r[7] = fmaf(ka1, a2,  sa0);
    r[8] = fmaf(k * a2, a2, c);
}

__global__ __launch_bounds__(TPB)
void twist2mat_one_kernel(const float4* __restrict__ in4,
                          float4* __restrict__ out4,
                          int n_elems)
{
    __shared__ float s_in [WARPS][TILES * 96];                 // 1536 B / warp
    __shared__ __align__(16) float s_out[WARPS][TILES * 288];  // 4608 B / warp

    const int lane = threadIdx.x & 31;
    const int wrp  = threadIdx.x >> 5;
    const long long wstart = ((long long)blockIdx.x * WARPS + wrp) * (32 * TILES);
    if (wstart >= n_elems) return;

    const float4* gin  = in4  + wstart / 4 * 3;   // wstart*3/4
    float4*       gout = out4 + wstart / 4 * 9;   // wstart*9/4

    const bool warp_full = (wstart + 32 * TILES <= n_elems);

    // ---- batched coalesced load: 96 float4 per warp (3 per lane) ----
    if (warp_full) {
        float4* s = (float4*)s_in[wrp];
#pragma unroll
        for (int j = 0; j < 3; j++)
            s[lane + 32 * j] = __ldcs(gin + lane + 32 * j);
    } else {
        const float* gf = (const float*)gin;
        int vf = (int)(n_elems - wstart) * 3;
        for (int i = lane; i < TILES * 96; i += 32)
            s_in[wrp][i] = (i < vf) ? gf[i] : 1.0f;   // pad, never stored
    }
    __syncwarp();

    if (warp_full) {
        // ---- compute all 4 tiles into one contiguous 4608B buffer ----
#pragma unroll
        for (int t = 0; t < TILES; t++) {
            const float* si = s_in[wrp] + t * 96;
            float x = si[3 * lane + 0];
            float y = si[3 * lane + 1];
            float z = si[3 * lane + 2];
            float r[9];
            rodrigues9(x, y, z, r);
            float* so = s_out[wrp] + t * 288;
#pragma unroll
            for (int i = 0; i < 9; i++)
                so[9 * lane + i] = r[i];              // stride-9 STS: conflict-free
        }
        __syncwarp();

        // ---- single TMA bulk store: 4608 contiguous bytes ----
        if (lane == 0) {
            asm volatile("fence.proxy.async.shared::cta;" ::: "memory");
            uint32_t src = (uint32_t)__cvta_generic_to_shared(s_out[wrp]);
            asm volatile(
                "cp.async.bulk.global.shared::cta.bulk_group [%0], [%1], %2;"
                :: "l"((void*)gout), "r"(src), "n"(4608) : "memory");
            asm volatile("cp.async.bulk.commit_group;" ::: "memory");
            // Wait only for the TMA engine to finish READING smem (safe for
            // smem reuse after CTA retire) — not for global write visibility.
            asm volatile("cp.async.bulk.wait_group.read 0;" ::: "memory");
        }
    } else {
        // ---- scalar-safe tail path (not hit for this shape) ----
        for (int t = 0; t < TILES; t++) {
            const long long tbase = wstart + 32LL * t;
            if (tbase >= n_elems) break;
            const float* si = s_in[wrp] + t * 96;
            float r[9];
            rodrigues9(si[3 * lane], si[3 * lane + 1], si[3 * lane + 2], r);
            float* so = s_out[wrp];
#pragma unroll
            for (int i = 0; i < 9; i++)
                so[9 * lane + i] = r[i];
            __syncwarp();
            float* gf = (float*)(gout + t * 72);
            long long ve = n_elems - tbase;
            int vf = (int)((ve < 32 ? ve : 32) * 9);
            for (int i = lane; i < vf; i += 32)
                gf[i] = so[i];
            __syncwarp();
        }
    }
}

extern "C" void kernel_launch(void* const* d_in, const int* in_sizes, int n_in,
                              void* d_out, int out_size)
{
    const float* twist = (const float*)d_in[0];
    float* out = (float*)d_out;

    int n_elems = in_sizes[0] / 3;                       // 8,388,608
    long long per_block = (long long)WARPS * 32 * TILES; // 1024
    int blocks = (int)((n_elems + per_block - 1) / per_block);

    twist2mat_one_kernel<<<blocks, TPB>>>((const float4*)twist, (float4*)out, n_elems);
}